// round 12
// baseline (speedup 1.0000x reference)
#include <cuda_runtime.h>
#include <cuda_bf16.h>
#include <cstdint>

#define T_STEPS 2048
#define B_SZ    32
#define D_SZ    512
#define H_SZ    512
#define G_SZ    2048
#define NBLK    128

// ---------------- device scratch ----------------
__device__ float g_xproj[(size_t)T_STEPS * G_SZ * B_SZ];     // [T][4H][B]
// m as packed bf16 pairs: P[buf][kp][b], uint32 = (m[2kp], m[2kp+1])
__device__ uint32_t g_mP_hi[2 * 256 * B_SZ];
__device__ uint32_t g_mP_lo[2 * 256 * B_SZ];
__device__ int g_bar;   // RMW arrival counter (read ONLY by block 0)
__device__ int g_go;    // broadcast release word (written ONLY by block 0)

// ---------------- helpers ----------------
#define CP_ASYNC16(dst_u32, src_ptr) \
    asm volatile("cp.async.cg.shared.global [%0], [%1], 16;\n" :: "r"(dst_u32), "l"(src_ptr))
#define CP_COMMIT() asm volatile("cp.async.commit_group;\n")
#define CP_WAIT(N)  asm volatile("cp.async.wait_group %0;\n" :: "n"(N))

__device__ __forceinline__ void split_tf(float x, uint32_t& hi, uint32_t& lo) {
    uint32_t h = __float_as_uint(x) & 0xffffe000u;
    hi = h;
    lo = __float_as_uint(x - __uint_as_float(h));
}
__device__ __forceinline__ void mma_tf32(float& d0, float& d1, float& d2, float& d3,
                                         uint32_t a0, uint32_t a1, uint32_t a2, uint32_t a3,
                                         uint32_t b0, uint32_t b1) {
    asm volatile(
        "mma.sync.aligned.m16n8k8.row.col.f32.tf32.tf32.f32 "
        "{%0,%1,%2,%3},{%4,%5,%6,%7},{%8,%9},{%0,%1,%2,%3};"
        : "+f"(d0), "+f"(d1), "+f"(d2), "+f"(d3)
        : "r"(a0), "r"(a1), "r"(a2), "r"(a3), "r"(b0), "r"(b1));
}
__device__ __forceinline__ void mma_bf16(float& d0, float& d1, float& d2, float& d3,
                                         uint32_t a0, uint32_t a1, uint32_t a2, uint32_t a3,
                                         uint32_t b0, uint32_t b1) {
    asm volatile(
        "mma.sync.aligned.m16n8k16.row.col.f32.bf16.bf16.f32 "
        "{%0,%1,%2,%3},{%4,%5,%6,%7},{%8,%9},{%0,%1,%2,%3};"
        : "+f"(d0), "+f"(d1), "+f"(d2), "+f"(d3)
        : "r"(a0), "r"(a1), "r"(a2), "r"(a3), "r"(b0), "r"(b1));
}
__device__ __forceinline__ uint32_t pack_bf2(float a, float b) {
    __nv_bfloat162 t = __floats2bfloat162_rn(a, b);   // a -> low half
    return *(uint32_t*)&t;
}

// ============ phase 1: x_proj GEMM (3xTF32, 3-stage pipeline) ============
#define XPA 2304
#define XPB 4352
#define XP_SMEM_FL (3 * (XPA + XPB))

__global__ __launch_bounds__(256, 2) void xproj_gemm(
    const float* __restrict__ A, const float* __restrict__ Bm,
    const float* __restrict__ bias)
{
    extern __shared__ float sm[];
    float* As = sm;
    float* Bs = sm + 3 * XPA;
    float* stage = Bs;

    const unsigned as_u32 = (unsigned)__cvta_generic_to_shared(As);
    const unsigned bs_u32 = (unsigned)__cvta_generic_to_shared(Bs);

    const int tid = threadIdx.x;

    if (blockIdx.x == 0 && blockIdx.y == 0) {   // fold reset
        if (tid == 0) { g_bar = 0; g_go = 0; }
        for (int i = tid; i < 256 * B_SZ; i += 256) { g_mP_hi[i] = 0u; g_mP_lo[i] = 0u; }
    }

    const int n0 = blockIdx.x * 128;
    const int m0 = blockIdx.y * 64;
    const int w   = tid >> 5;
    const int l   = tid & 31;
    const int gid = l >> 2;
    const int tig = l & 3;
    const int nw  = w * 16;

    auto issue = [&](int it, int buf) {
        const int kc = it * 32;
#pragma unroll
        for (int i = 0; i < 2; i++) {
            int idx = tid + i * 256;
            int m = idx >> 3, kq = (idx & 7) << 2;
            CP_ASYNC16(as_u32 + (unsigned)((buf * XPA + m * 36 + kq) * 4),
                       A + (size_t)(m0 + m) * D_SZ + kc + kq);
        }
#pragma unroll
        for (int i = 0; i < 4; i++) {
            int idx = tid + i * 256;
            int k = idx >> 5, nq = (idx & 31) << 2;
            CP_ASYNC16(bs_u32 + (unsigned)((buf * XPB + k * 136 + nq) * 4),
                       Bm + (size_t)(kc + k) * G_SZ + n0 + nq);
        }
        CP_COMMIT();
    };

    float acc1[4][2][4], acc2[4][2][4];
#pragma unroll
    for (int mt = 0; mt < 4; mt++)
#pragma unroll
        for (int nt = 0; nt < 2; nt++)
#pragma unroll
            for (int r = 0; r < 4; r++) { acc1[mt][nt][r] = 0.0f; acc2[mt][nt][r] = 0.0f; }

    issue(0, 0);
    issue(1, 1);

#pragma unroll 1
    for (int it = 0; it < 16; it++) {
        if (it < 15) { CP_WAIT(1); } else { CP_WAIT(0); }
        __syncthreads();
        if (it + 2 < 16) issue(it + 2, (it + 2) % 3);

        const float* Ab = As + (it % 3) * XPA;
        const float* Bb = Bs + (it % 3) * XPB;

#pragma unroll
        for (int kt = 0; kt < 4; kt++) {
            uint32_t bh[2][2], bl[2][2];
#pragma unroll
            for (int nt = 0; nt < 2; nt++) {
                float w0 = Bb[(kt * 8 + tig) * 136 + nw + nt * 8 + gid];
                float w1 = Bb[(kt * 8 + tig + 4) * 136 + nw + nt * 8 + gid];
                split_tf(w0, bh[nt][0], bl[nt][0]);
                split_tf(w1, bh[nt][1], bl[nt][1]);
            }
#pragma unroll
            for (int mt = 0; mt < 4; mt++) {
                float x0 = Ab[(mt * 16 + gid) * 36 + kt * 8 + tig];
                float x1 = Ab[(mt * 16 + gid + 8) * 36 + kt * 8 + tig];
                float x2 = Ab[(mt * 16 + gid) * 36 + kt * 8 + tig + 4];
                float x3 = Ab[(mt * 16 + gid + 8) * 36 + kt * 8 + tig + 4];
                uint32_t ah0, al0, ah1, al1, ah2, al2, ah3, al3;
                split_tf(x0, ah0, al0); split_tf(x1, ah1, al1);
                split_tf(x2, ah2, al2); split_tf(x3, ah3, al3);
#pragma unroll
                for (int nt = 0; nt < 2; nt++) {
                    mma_tf32(acc1[mt][nt][0], acc1[mt][nt][1], acc1[mt][nt][2], acc1[mt][nt][3],
                             ah0, ah1, ah2, ah3, bh[nt][0], bh[nt][1]);
                    mma_tf32(acc2[mt][nt][0], acc2[mt][nt][1], acc2[mt][nt][2], acc2[mt][nt][3],
                             ah0, ah1, ah2, ah3, bl[nt][0], bl[nt][1]);
                    mma_tf32(acc2[mt][nt][0], acc2[mt][nt][1], acc2[mt][nt][2], acc2[mt][nt][3],
                             al0, al1, al2, al3, bh[nt][0], bh[nt][1]);
                }
            }
        }
    }
    __syncthreads();

#pragma unroll
    for (int mt = 0; mt < 4; mt++)
#pragma unroll
        for (int nt = 0; nt < 2; nt++) {
            int m = mt * 16 + gid;
            int n = nw + nt * 8 + tig * 2;
            stage[n * 68 + m]           = acc1[mt][nt][0] + acc2[mt][nt][0];
            stage[(n + 1) * 68 + m]     = acc1[mt][nt][1] + acc2[mt][nt][1];
            stage[n * 68 + m + 8]       = acc1[mt][nt][2] + acc2[mt][nt][2];
            stage[(n + 1) * 68 + m + 8] = acc1[mt][nt][3] + acc2[mt][nt][3];
        }
    __syncthreads();

#pragma unroll
    for (int i = 0; i < 8; i++) {
        int idx = tid + i * 256;
        int n = idx >> 4, mq = (idx & 15) << 2;
        float4 v = *(float4*)&stage[n * 68 + mq];
        float bb = bias[n0 + n];
        v.x += bb; v.y += bb; v.z += bb; v.w += bb;
        int mg = m0 + mq;
        int t = mg >> 5, b = mg & 31;
        *(float4*)&g_xproj[((size_t)t * G_SZ + n0 + n) * B_SZ + b] = v;
    }
}

// ============ phase 2: persistent recurrence (bf16-pair k16) ============
#define MPS 40
#define MHI_OFF_B 0
#define MLO_OFF_B (256 * MPS * 4)               // 40960
#define RED_OFF_B (2 * 256 * MPS * 4)           // 81920
#define XP_OFF_B  (RED_OFF_B + 16 * 576 * 4)    // 118784
#define PAD_OFF_B (XP_OFF_B + 4096)             // 122880
#define MST_OFF_B (PAD_OFF_B + 256)             // 123136
#define M2F_OFF_B (MST_OFF_B + 512)             // 123648  fp32 m2 stage [4][32]
#define SMEM_BYTES_L (M2F_OFF_B + 512)          // 124160

__device__ __forceinline__ float fsig(float x)  { return 1.0f / (1.0f + __expf(-x)); }
__device__ __forceinline__ float ftanh(float x) { return 1.0f - 2.0f / (__expf(2.0f * x) + 1.0f); }

__global__ __launch_bounds__(512, 1) void lstm_kernel(
    const float* __restrict__ paddings,
    const float* __restrict__ W_h,
    float* __restrict__ out,
    int write_final)
{
    extern __shared__ char smc[];
    const uint32_t* mhi_s = (const uint32_t*)(smc + MHI_OFF_B);
    const uint32_t* mlo_s = (const uint32_t*)(smc + MLO_OFF_B);
    float* red   = (float*)(smc + RED_OFF_B);
    float* xp_s  = (float*)(smc + XP_OFF_B);
    float* pad_s = (float*)(smc + PAD_OFF_B);
    __nv_bfloat16* mst_hi = (__nv_bfloat16*)(smc + MST_OFF_B);
    __nv_bfloat16* mst_lo = (__nv_bfloat16*)(smc + MST_OFF_B + 256);
    float* m2f_s = (float*)(smc + M2F_OFF_B);   // [4 j][32 b]

    const unsigned smem_u32 = (unsigned)__cvta_generic_to_shared(smc);
    const unsigned mhi_u32  = smem_u32 + MHI_OFF_B;
    const unsigned mlo_u32  = smem_u32 + MLO_OFF_B;
    const unsigned xp_u32   = smem_u32 + XP_OFF_B;
    const unsigned pad_u32  = smem_u32 + PAD_OFF_B;

    const int tid = threadIdx.x;
    const int bid = blockIdx.x;
    const int h_base = bid * 4;

    const int l   = tid & 31;
    const int w   = tid >> 5;
    const int gid = l >> 2;
    const int tig = l & 3;

    // ---- W fragments as bf16 pairs (registers) ----
    uint32_t Wh[2][2][2], Wl[2][2][2];
#pragma unroll
    for (int J = 0; J < 2; J++)
#pragma unroll
        for (int nt = 0; nt < 2; nt++)
#pragma unroll
            for (int r = 0; r < 2; r++) {
                int k  = w * 32 + J * 16 + tig * 2 + r * 8;
                int cc = nt * 8 + gid;
                int g  = cc & 3;
                int j4 = cc >> 2;
                const float* wp = W_h + (size_t)g * H_SZ + h_base + j4;
                float w0 = wp[(size_t)k * G_SZ];
                float w1 = wp[(size_t)(k + 1) * G_SZ];
                float h0 = __bfloat162float(__float2bfloat16_rn(w0));
                float h1 = __bfloat162float(__float2bfloat16_rn(w1));
                Wh[J][nt][r] = pack_bf2(h0, h1);
                Wl[J][nt][r] = pack_bf2(w0 - h0, w1 - h1);
            }

    // cell ownership (tid<128): b=tid&31, j=tid>>5
    const int cb  = tid & 31;
    const int cj  = tid >> 5;
    const int h_o = h_base + cj;

    // xp loader coords (tid<128)
    const int xp_cc = tid >> 3;
    const int xp_q  = (tid & 7) << 2;
    const float* xp_src_base = g_xproj +
        ((size_t)((xp_cc & 3) * H_SZ + h_base + (xp_cc >> 2))) * B_SZ + xp_q;

    // m loader coords
    const int mrow = l >> 2;
    const int mq16 = (l & 3) * 16;

    // prologue: xp(0) + pad(0)
    if (tid < 128)
        CP_ASYNC16(xp_u32 + (unsigned)((xp_cc * B_SZ + xp_q) * 4), xp_src_base);
    if (tid < 8)
        CP_ASYNC16(pad_u32 + (unsigned)(tid * 16), paddings + tid * 4);
    CP_COMMIT();

    float c_reg = 0.0f, m_prev = 0.0f;

#pragma unroll 1
    for (int s = 0; s < T_STEPS; s++) {
        const int pb = s & 1, nb = pb ^ 1;
        const char* srcP_hi = (const char*)(g_mP_hi + pb * 256 * B_SZ);
        const char* srcP_lo = (const char*)(g_mP_lo + pb * 256 * B_SZ);

        // ---- 2 warp-private m groups (coalesced) ----
#pragma unroll
        for (int J = 0; J < 2; J++) {
            const int kp = w * 16 + J * 8 + mrow;
            const unsigned sb = (unsigned)(kp * 128 + mq16);
            const unsigned db = (unsigned)(kp * MPS * 4 + mq16);
            CP_ASYNC16(mhi_u32 + db,      srcP_hi + sb);
            CP_ASYNC16(mhi_u32 + db + 64, srcP_hi + sb + 64);
            CP_ASYNC16(mlo_u32 + db,      srcP_lo + sb);
            CP_ASYNC16(mlo_u32 + db + 64, srcP_lo + sb + 64);
            CP_COMMIT();
        }
        // ---- xp(s+1)+pad(s+1) prefetch ----
        if (s + 1 < T_STEPS) {
            if (tid < 128)
                CP_ASYNC16(xp_u32 + (unsigned)(((nb * 512) + xp_cc * B_SZ + xp_q) * 4),
                           xp_src_base + (size_t)(s + 1) * G_SZ * B_SZ);
            if (tid < 8)
                CP_ASYNC16(pad_u32 + (unsigned)((nb * 32 + tid * 4) * 4),
                           paddings + (size_t)(s + 1) * B_SZ + tid * 4);
        }
        CP_COMMIT();

        float acc1[2][2][4], acc2[2][2][4];
#pragma unroll
        for (int mt = 0; mt < 2; mt++)
#pragma unroll
            for (int nt = 0; nt < 2; nt++)
#pragma unroll
                for (int r = 0; r < 4; r++) { acc1[mt][nt][r] = 0.0f; acc2[mt][nt][r] = 0.0f; }

        // ---- 2 mma chunks, warp-paced ----
#define MMA_CHUNK(J, WN)                                                           \
        {                                                                          \
            CP_WAIT(WN);                                                           \
            __syncwarp();                                                          \
            const int i0 = (w * 16 + (J) * 8 + tig) * MPS + gid;                   \
            const int i2 = i0 + 4 * MPS;                                           \
            _Pragma("unroll")                                                      \
            for (int mt = 0; mt < 2; mt++) {                                       \
                const int o = mt * 16;                                             \
                uint32_t ah0 = mhi_s[i0 + o],     ah1 = mhi_s[i0 + o + 8];         \
                uint32_t ah2 = mhi_s[i2 + o],     ah3 = mhi_s[i2 + o + 8];         \
                uint32_t al0 = mlo_s[i0 + o],     al1 = mlo_s[i0 + o + 8];         \
                uint32_t al2 = mlo_s[i2 + o],     al3 = mlo_s[i2 + o + 8];         \
                _Pragma("unroll")                                                  \
                for (int nt = 0; nt < 2; nt++) {                                   \
                    mma_bf16(acc1[mt][nt][0], acc1[mt][nt][1],                     \
                             acc1[mt][nt][2], acc1[mt][nt][3],                     \
                             ah0, ah1, ah2, ah3, Wh[J][nt][0], Wh[J][nt][1]);      \
                    mma_bf16(acc2[mt][nt][0], acc2[mt][nt][1],                     \
                             acc2[mt][nt][2], acc2[mt][nt][3],                     \
                             ah0, ah1, ah2, ah3, Wl[J][nt][0], Wl[J][nt][1]);      \
                    mma_bf16(acc2[mt][nt][0], acc2[mt][nt][1],                     \
                             acc2[mt][nt][2], acc2[mt][nt][3],                     \
                             al0, al1, al2, al3, Wh[J][nt][0], Wh[J][nt][1]);      \
                }                                                                  \
            }                                                                      \
        }

        MMA_CHUNK(0, 2)
        MMA_CHUNK(1, 1)
#undef MMA_CHUNK

        // partials -> red[w][cc][36]
        {
            float* rp = red + w * 576;
#pragma unroll
            for (int mt = 0; mt < 2; mt++)
#pragma unroll
                for (int nt = 0; nt < 2; nt++) {
                    const int b  = mt * 16 + gid;
                    const int cc = nt * 8 + tig * 2;
                    rp[cc * 36 + b]           = acc1[mt][nt][0] + acc2[mt][nt][0];
                    rp[(cc + 1) * 36 + b]     = acc1[mt][nt][1] + acc2[mt][nt][1];
                    rp[cc * 36 + b + 8]       = acc1[mt][nt][2] + acc2[mt][nt][2];
                    rp[(cc + 1) * 36 + b + 8] = acc1[mt][nt][3] + acc2[mt][nt][3];
                }
        }
        __syncthreads();

        // ---- cell tail (warps 0-3) ----
        float m2 = 0.0f, c2 = 0.0f;
        if (tid < 128) {
            float gate[4];
#pragma unroll
            for (int g = 0; g < 4; g++) {
                const int cc = cj * 4 + g;
                const float* rb = red + cc * 36 + cb;
                float sum = xp_s[pb * 512 + cc * 32 + cb];
#pragma unroll
                for (int ww = 0; ww < 16; ww++) sum += rb[ww * 576];
                gate[g] = sum;
            }
            float p  = pad_s[pb * 32 + cb];
            float ii = fsig(gate[0]), ff = fsig(gate[1]);
            float gg = ftanh(gate[2]), oo = fsig(gate[3]);
            float cn = ff * c_reg + ii * gg;
            float mn = oo * ftanh(cn);
            m2 = mn + (m_prev - mn) * p;
            c2 = cn + (c_reg - cn) * p;
            c_reg = c2;
            m_prev = m2;

            float hif = __bfloat162float(__float2bfloat16_rn(m2));
            mst_hi[cj * 32 + cb] = __float2bfloat16_rn(m2);
            mst_lo[cj * 32 + cb] = __float2bfloat16_rn(m2 - hif);
            m2f_s[cj * 32 + cb] = m2;   // fp32 stage for coalesced out

            asm volatile("bar.sync 1, 128;" ::: "memory");
            // pack h-pairs -> global (tid<64): kp = 2*bid + hpair
            if (tid < 64) {
                const int hpair = tid >> 5, b = tid & 31;
                float h0 = __bfloat162float(mst_hi[(2 * hpair) * 32 + b]);
                float h1 = __bfloat162float(mst_hi[(2 * hpair + 1) * 32 + b]);
                float l0 = __bfloat162float(mst_lo[(2 * hpair) * 32 + b]);
                float l1 = __bfloat162float(mst_lo[(2 * hpair + 1) * 32 + b]);
                const int gi = nb * 256 * B_SZ + (2 * bid + hpair) * B_SZ + b;
                g_mP_hi[gi] = pack_bf2(h0, h1);
                g_mP_lo[gi] = pack_bf2(l0, l1);
            }
            // coalesced out: 32 threads write float4 (4 consecutive h per b)
            if (tid < 32) {
                float4 o4 = make_float4(m2f_s[tid], m2f_s[32 + tid],
                                        m2f_s[64 + tid], m2f_s[96 + tid]);
                *(float4*)&out[((size_t)s * B_SZ + tid) * H_SZ + h_base] = o4;
            }
            asm volatile("bar.sync 1, 128;" ::: "memory");
            if (tid == 0) { __threadfence(); atomicAdd(&g_bar, 1); }

            if (write_final && s == T_STEPS - 1) {
                size_t base = (size_t)T_STEPS * B_SZ * H_SZ;
                out[base + (size_t)cb * H_SZ + h_o] = m2;
                out[base + (size_t)B_SZ * H_SZ + (size_t)cb * H_SZ + h_o] = c2;
            }
        }

        // ---- leader-release grid barrier ----
        if (bid == 0 && tid == 0) {
            const int target = NBLK * (s + 1);
            while (*(volatile int*)&g_bar < target) { }
            __threadfence();
            *(volatile int*)&g_go = s + 1;   // broadcast release (clean line)
        }
        if (tid == 0) {
            while (*(volatile int*)&g_go < s + 1) { }
            __threadfence();
        }
        __syncthreads();
    }
}

// ---------------- launch ----------------
extern "C" void kernel_launch(void* const* d_in, const int* in_sizes, int n_in,
                              void* d_out, int out_size)
{
    const float* input = (const float*)d_in[0];
    const float* padd  = (const float*)d_in[1];
    const float* W_x   = (const float*)d_in[2];
    const float* W_h   = (const float*)d_in[3];
    const float* bias  = (const float*)d_in[4];
    float* out = (float*)d_out;

    const size_t xp_smem = (size_t)XP_SMEM_FL * sizeof(float);
    cudaFuncSetAttribute(xproj_gemm, cudaFuncAttributeMaxDynamicSharedMemorySize, (int)xp_smem);
    cudaFuncSetAttribute(lstm_kernel, cudaFuncAttributeMaxDynamicSharedMemorySize, SMEM_BYTES_L);

    int write_final =
        ((size_t)out_size >= (size_t)T_STEPS * B_SZ * H_SZ + 2u * B_SZ * H_SZ) ? 1 : 0;

    xproj_gemm<<<dim3(G_SZ / 128, (T_STEPS * B_SZ) / 64), 256, xp_smem>>>(input, W_x, bias);
    lstm_kernel<<<NBLK, 512, SMEM_BYTES_L>>>(padd, W_h, out, write_final);
}

// round 13
// speedup vs baseline: 1.2244x; 1.2244x over previous
#include <cuda_runtime.h>
#include <cuda_bf16.h>
#include <cstdint>

#define T_STEPS 2048
#define B_SZ    32
#define D_SZ    512
#define H_SZ    512
#define G_SZ    2048
#define NBLK    128

// ---------------- device scratch ----------------
__device__ float g_xproj[(size_t)T_STEPS * G_SZ * B_SZ];     // [T][4H][B]
// m as packed bf16 pairs: P[buf][kp][b], uint32 = (m[2kp], m[2kp+1])
__device__ uint32_t g_mP_hi[2 * 256 * B_SZ];
__device__ uint32_t g_mP_lo[2 * 256 * B_SZ];
__device__ int g_bar;

// ---------------- helpers ----------------
#define CP_ASYNC16(dst_u32, src_ptr) \
    asm volatile("cp.async.cg.shared.global [%0], [%1], 16;\n" :: "r"(dst_u32), "l"(src_ptr))
#define CP_COMMIT() asm volatile("cp.async.commit_group;\n")
#define CP_WAIT(N)  asm volatile("cp.async.wait_group %0;\n" :: "n"(N))

__device__ __forceinline__ void mma_bf16(float& d0, float& d1, float& d2, float& d3,
                                         uint32_t a0, uint32_t a1, uint32_t a2, uint32_t a3,
                                         uint32_t b0, uint32_t b1) {
    asm volatile(
        "mma.sync.aligned.m16n8k16.row.col.f32.bf16.bf16.f32 "
        "{%0,%1,%2,%3},{%4,%5,%6,%7},{%8,%9},{%0,%1,%2,%3};"
        : "+f"(d0), "+f"(d1), "+f"(d2), "+f"(d3)
        : "r"(a0), "r"(a1), "r"(a2), "r"(a3), "r"(b0), "r"(b1));
}
__device__ __forceinline__ uint32_t pack_bf2(float a, float b) {
    __nv_bfloat162 t = __floats2bfloat162_rn(a, b);   // a -> low half
    return *(uint32_t*)&t;
}
// split a float pair into bf16-hi pair and exact-residual bf16-lo pair
__device__ __forceinline__ void split_pair(float f0, float f1, uint32_t& hi, uint32_t& lo) {
    float h0 = __bfloat162float(__float2bfloat16_rn(f0));
    float h1 = __bfloat162float(__float2bfloat16_rn(f1));
    hi = pack_bf2(h0, h1);
    lo = pack_bf2(f0 - h0, f1 - h1);
}

// ============ phase 1: x_proj GEMM (bf16-pair 3-mma k16, 3-stage) ============
#define XPA 2304   // 64*36 fp32 per A buffer
#define XPB 4352   // 32*136 fp32 per B buffer
#define XP_SMEM_FL (3 * (XPA + XPB))

__global__ __launch_bounds__(256, 2) void xproj_gemm(
    const float* __restrict__ A, const float* __restrict__ Bm,
    const float* __restrict__ bias)
{
    extern __shared__ float sm[];
    float* As = sm;
    float* Bs = sm + 3 * XPA;
    float* stage = Bs;             // epilogue overlay (128*68 = 8704 <= 13056)

    const unsigned as_u32 = (unsigned)__cvta_generic_to_shared(As);
    const unsigned bs_u32 = (unsigned)__cvta_generic_to_shared(Bs);

    const int tid = threadIdx.x;

    if (blockIdx.x == 0 && blockIdx.y == 0) {   // fold reset
        if (tid == 0) g_bar = 0;
        for (int i = tid; i < 256 * B_SZ; i += 256) { g_mP_hi[i] = 0u; g_mP_lo[i] = 0u; }
    }

    const int n0 = blockIdx.x * 128;
    const int m0 = blockIdx.y * 64;
    const int w   = tid >> 5;
    const int l   = tid & 31;
    const int gid = l >> 2;
    const int tig = l & 3;
    const int nw  = w * 16;

    auto issue = [&](int it, int buf) {
        const int kc = it * 32;
#pragma unroll
        for (int i = 0; i < 2; i++) {
            int idx = tid + i * 256;
            int m = idx >> 3, kq = (idx & 7) << 2;
            CP_ASYNC16(as_u32 + (unsigned)((buf * XPA + m * 36 + kq) * 4),
                       A + (size_t)(m0 + m) * D_SZ + kc + kq);
        }
#pragma unroll
        for (int i = 0; i < 4; i++) {
            int idx = tid + i * 256;
            int k = idx >> 5, nq = (idx & 31) << 2;
            CP_ASYNC16(bs_u32 + (unsigned)((buf * XPB + k * 136 + nq) * 4),
                       Bm + (size_t)(kc + k) * G_SZ + n0 + nq);
        }
        CP_COMMIT();
    };

    float acc[4][2][4];
#pragma unroll
    for (int mt = 0; mt < 4; mt++)
#pragma unroll
        for (int nt = 0; nt < 2; nt++)
#pragma unroll
            for (int r = 0; r < 4; r++) acc[mt][nt][r] = 0.0f;

    issue(0, 0);
    issue(1, 1);

#pragma unroll 1
    for (int it = 0; it < 16; it++) {
        if (it < 15) { CP_WAIT(1); } else { CP_WAIT(0); }
        __syncthreads();
        if (it + 2 < 16) issue(it + 2, (it + 2) % 3);

        const float* Ab = As + (it % 3) * XPA;
        const float* Bb = Bs + (it % 3) * XPB;

#pragma unroll
        for (int c = 0; c < 2; c++) {           // two k16 sub-chunks
            const int k0 = c * 16 + tig * 2;
            // B fragments (hi/lo): reg r=0 -> k rows (k0,k0+1); r=1 -> (k0+8,k0+9)
            uint32_t bh[2][2], bl[2][2];
#pragma unroll
            for (int nt = 0; nt < 2; nt++) {
                const int n = nw + nt * 8 + gid;
                float b00 = Bb[k0 * 136 + n];
                float b01 = Bb[(k0 + 1) * 136 + n];
                float b10 = Bb[(k0 + 8) * 136 + n];
                float b11 = Bb[(k0 + 9) * 136 + n];
                split_pair(b00, b01, bh[nt][0], bl[nt][0]);
                split_pair(b10, b11, bh[nt][1], bl[nt][1]);
            }
#pragma unroll
            for (int mt = 0; mt < 4; mt++) {
                const int row0 = mt * 16 + gid;
                float2 f0 = *(const float2*)&Ab[row0 * 36 + k0];
                float2 f1 = *(const float2*)&Ab[(row0 + 8) * 36 + k0];
                float2 f2 = *(const float2*)&Ab[row0 * 36 + k0 + 8];
                float2 f3 = *(const float2*)&Ab[(row0 + 8) * 36 + k0 + 8];
                uint32_t ah0, al0, ah1, al1, ah2, al2, ah3, al3;
                split_pair(f0.x, f0.y, ah0, al0);
                split_pair(f1.x, f1.y, ah1, al1);
                split_pair(f2.x, f2.y, ah2, al2);
                split_pair(f3.x, f3.y, ah3, al3);
#pragma unroll
                for (int nt = 0; nt < 2; nt++) {
                    mma_bf16(acc[mt][nt][0], acc[mt][nt][1], acc[mt][nt][2], acc[mt][nt][3],
                             ah0, ah1, ah2, ah3, bh[nt][0], bh[nt][1]);
                    mma_bf16(acc[mt][nt][0], acc[mt][nt][1], acc[mt][nt][2], acc[mt][nt][3],
                             ah0, ah1, ah2, ah3, bl[nt][0], bl[nt][1]);
                    mma_bf16(acc[mt][nt][0], acc[mt][nt][1], acc[mt][nt][2], acc[mt][nt][3],
                             al0, al1, al2, al3, bh[nt][0], bh[nt][1]);
                }
            }
        }
    }
    __syncthreads();

#pragma unroll
    for (int mt = 0; mt < 4; mt++)
#pragma unroll
        for (int nt = 0; nt < 2; nt++) {
            int m = mt * 16 + gid;
            int n = nw + nt * 8 + tig * 2;
            stage[n * 68 + m]           = acc[mt][nt][0];
            stage[(n + 1) * 68 + m]     = acc[mt][nt][1];
            stage[n * 68 + m + 8]       = acc[mt][nt][2];
            stage[(n + 1) * 68 + m + 8] = acc[mt][nt][3];
        }
    __syncthreads();

#pragma unroll
    for (int i = 0; i < 8; i++) {
        int idx = tid + i * 256;
        int n = idx >> 4, mq = (idx & 15) << 2;
        float4 v = *(float4*)&stage[n * 68 + mq];
        float bb = bias[n0 + n];
        v.x += bb; v.y += bb; v.z += bb; v.w += bb;
        int mg = m0 + mq;
        int t = mg >> 5, b = mg & 31;
        *(float4*)&g_xproj[((size_t)t * G_SZ + n0 + n) * B_SZ + b] = v;
    }
}

// ============ phase 2: persistent recurrence (R9 verbatim + coalesced out) ==
#define MPS 40
#define MHI_OFF_B 0
#define MLO_OFF_B (256 * MPS * 4)               // 40960
#define RED_OFF_B (2 * 256 * MPS * 4)           // 81920
#define XP_OFF_B  (RED_OFF_B + 16 * 576 * 4)    // 118784
#define PAD_OFF_B (XP_OFF_B + 4096)             // 122880
#define MST_OFF_B (PAD_OFF_B + 256)             // 123136
#define M2F_OFF_B (MST_OFF_B + 512)             // 123648
#define SMEM_BYTES_L (M2F_OFF_B + 512)          // 124160

__device__ __forceinline__ float fsig(float x)  { return 1.0f / (1.0f + __expf(-x)); }
__device__ __forceinline__ float ftanh(float x) { return 1.0f - 2.0f / (__expf(2.0f * x) + 1.0f); }

__global__ __launch_bounds__(512, 1) void lstm_kernel(
    const float* __restrict__ paddings,
    const float* __restrict__ W_h,
    float* __restrict__ out,
    int write_final)
{
    extern __shared__ char smc[];
    const uint32_t* mhi_s = (const uint32_t*)(smc + MHI_OFF_B);
    const uint32_t* mlo_s = (const uint32_t*)(smc + MLO_OFF_B);
    float* red   = (float*)(smc + RED_OFF_B);
    float* xp_s  = (float*)(smc + XP_OFF_B);
    float* pad_s = (float*)(smc + PAD_OFF_B);
    __nv_bfloat16* mst_hi = (__nv_bfloat16*)(smc + MST_OFF_B);
    __nv_bfloat16* mst_lo = (__nv_bfloat16*)(smc + MST_OFF_B + 256);
    float* m2f_s = (float*)(smc + M2F_OFF_B);   // [4 j][32 b]

    const unsigned smem_u32 = (unsigned)__cvta_generic_to_shared(smc);
    const unsigned mhi_u32  = smem_u32 + MHI_OFF_B;
    const unsigned mlo_u32  = smem_u32 + MLO_OFF_B;
    const unsigned xp_u32   = smem_u32 + XP_OFF_B;
    const unsigned pad_u32  = smem_u32 + PAD_OFF_B;

    const int tid = threadIdx.x;
    const int bid = blockIdx.x;
    const int h_base = bid * 4;

    const int l   = tid & 31;
    const int w   = tid >> 5;
    const int gid = l >> 2;
    const int tig = l & 3;

    // ---- W fragments as bf16 pairs (registers) ----
    uint32_t Wh[2][2][2], Wl[2][2][2];
#pragma unroll
    for (int J = 0; J < 2; J++)
#pragma unroll
        for (int nt = 0; nt < 2; nt++)
#pragma unroll
            for (int r = 0; r < 2; r++) {
                int k  = w * 32 + J * 16 + tig * 2 + r * 8;
                int cc = nt * 8 + gid;
                int g  = cc & 3;
                int j4 = cc >> 2;
                const float* wp = W_h + (size_t)g * H_SZ + h_base + j4;
                float w0 = wp[(size_t)k * G_SZ];
                float w1 = wp[(size_t)(k + 1) * G_SZ];
                split_pair(w0, w1, Wh[J][nt][r], Wl[J][nt][r]);
            }

    // cell ownership (tid<128): b=tid&31, j=tid>>5
    const int cb  = tid & 31;
    const int cj  = tid >> 5;
    const int h_o = h_base + cj;

    // xp loader coords (tid<128)
    const int xp_cc = tid >> 3;
    const int xp_q  = (tid & 7) << 2;
    const float* xp_src_base = g_xproj +
        ((size_t)((xp_cc & 3) * H_SZ + h_base + (xp_cc >> 2))) * B_SZ + xp_q;

    // m loader coords
    const int mrow = l >> 2;
    const int mq16 = (l & 3) * 16;

    // prologue: xp(0) + pad(0)
    if (tid < 128)
        CP_ASYNC16(xp_u32 + (unsigned)((xp_cc * B_SZ + xp_q) * 4), xp_src_base);
    if (tid < 8)
        CP_ASYNC16(pad_u32 + (unsigned)(tid * 16), paddings + tid * 4);
    CP_COMMIT();

    float c_reg = 0.0f, m_prev = 0.0f;

#pragma unroll 1
    for (int s = 0; s < T_STEPS; s++) {
        const int pb = s & 1, nb = pb ^ 1;
        const char* srcP_hi = (const char*)(g_mP_hi + pb * 256 * B_SZ);
        const char* srcP_lo = (const char*)(g_mP_lo + pb * 256 * B_SZ);

        // ---- 2 warp-private m groups (coalesced) ----
#pragma unroll
        for (int J = 0; J < 2; J++) {
            const int kp = w * 16 + J * 8 + mrow;
            const unsigned sb = (unsigned)(kp * 128 + mq16);
            const unsigned db = (unsigned)(kp * MPS * 4 + mq16);
            CP_ASYNC16(mhi_u32 + db,      srcP_hi + sb);
            CP_ASYNC16(mhi_u32 + db + 64, srcP_hi + sb + 64);
            CP_ASYNC16(mlo_u32 + db,      srcP_lo + sb);
            CP_ASYNC16(mlo_u32 + db + 64, srcP_lo + sb + 64);
            CP_COMMIT();
        }
        // ---- xp(s+1)+pad(s+1) prefetch ----
        if (s + 1 < T_STEPS) {
            if (tid < 128)
                CP_ASYNC16(xp_u32 + (unsigned)(((nb * 512) + xp_cc * B_SZ + xp_q) * 4),
                           xp_src_base + (size_t)(s + 1) * G_SZ * B_SZ);
            if (tid < 8)
                CP_ASYNC16(pad_u32 + (unsigned)((nb * 32 + tid * 4) * 4),
                           paddings + (size_t)(s + 1) * B_SZ + tid * 4);
        }
        CP_COMMIT();

        float acc1[2][2][4], acc2[2][2][4];
#pragma unroll
        for (int mt = 0; mt < 2; mt++)
#pragma unroll
            for (int nt = 0; nt < 2; nt++)
#pragma unroll
                for (int r = 0; r < 4; r++) { acc1[mt][nt][r] = 0.0f; acc2[mt][nt][r] = 0.0f; }

        // ---- 2 mma chunks, warp-paced ----
#define MMA_CHUNK(J, WN)                                                           \
        {                                                                          \
            CP_WAIT(WN);                                                           \
            __syncwarp();                                                          \
            const int i0 = (w * 16 + (J) * 8 + tig) * MPS + gid;                   \
            const int i2 = i0 + 4 * MPS;                                           \
            _Pragma("unroll")                                                      \
            for (int mt = 0; mt < 2; mt++) {                                       \
                const int o = mt * 16;                                             \
                uint32_t ah0 = mhi_s[i0 + o],     ah1 = mhi_s[i0 + o + 8];         \
                uint32_t ah2 = mhi_s[i2 + o],     ah3 = mhi_s[i2 + o + 8];         \
                uint32_t al0 = mlo_s[i0 + o],     al1 = mlo_s[i0 + o + 8];         \
                uint32_t al2 = mlo_s[i2 + o],     al3 = mlo_s[i2 + o + 8];         \
                _Pragma("unroll")                                                  \
                for (int nt = 0; nt < 2; nt++) {                                   \
                    mma_bf16(acc1[mt][nt][0], acc1[mt][nt][1],                     \
                             acc1[mt][nt][2], acc1[mt][nt][3],                     \
                             ah0, ah1, ah2, ah3, Wh[J][nt][0], Wh[J][nt][1]);      \
                    mma_bf16(acc2[mt][nt][0], acc2[mt][nt][1],                     \
                             acc2[mt][nt][2], acc2[mt][nt][3],                     \
                             ah0, ah1, ah2, ah3, Wl[J][nt][0], Wl[J][nt][1]);      \
                    mma_bf16(acc2[mt][nt][0], acc2[mt][nt][1],                     \
                             acc2[mt][nt][2], acc2[mt][nt][3],                     \
                             al0, al1, al2, al3, Wh[J][nt][0], Wh[J][nt][1]);      \
                }                                                                  \
            }                                                                      \
        }

        MMA_CHUNK(0, 2)
        MMA_CHUNK(1, 1)
#undef MMA_CHUNK

        // partials -> red[w][cc][36]
        {
            float* rp = red + w * 576;
#pragma unroll
            for (int mt = 0; mt < 2; mt++)
#pragma unroll
                for (int nt = 0; nt < 2; nt++) {
                    const int b  = mt * 16 + gid;
                    const int cc = nt * 8 + tig * 2;
                    rp[cc * 36 + b]           = acc1[mt][nt][0] + acc2[mt][nt][0];
                    rp[(cc + 1) * 36 + b]     = acc1[mt][nt][1] + acc2[mt][nt][1];
                    rp[cc * 36 + b + 8]       = acc1[mt][nt][2] + acc2[mt][nt][2];
                    rp[(cc + 1) * 36 + b + 8] = acc1[mt][nt][3] + acc2[mt][nt][3];
                }
        }
        __syncthreads();

        // ---- cell tail (warps 0-3) ----
        float m2 = 0.0f, c2 = 0.0f;
        if (tid < 128) {
            float gate[4];
#pragma unroll
            for (int g = 0; g < 4; g++) {
                const int cc = cj * 4 + g;
                const float* rb = red + cc * 36 + cb;
                float sum = xp_s[pb * 512 + cc * 32 + cb];
#pragma unroll
                for (int ww = 0; ww < 16; ww++) sum += rb[ww * 576];
                gate[g] = sum;
            }
            float p  = pad_s[pb * 32 + cb];
            float ii = fsig(gate[0]), ff = fsig(gate[1]);
            float gg = ftanh(gate[2]), oo = fsig(gate[3]);
            float cn = ff * c_reg + ii * gg;
            float mn = oo * ftanh(cn);
            m2 = mn + (m_prev - mn) * p;
            c2 = cn + (c_reg - cn) * p;
            c_reg = c2;
            m_prev = m2;

            float hif = __bfloat162float(__float2bfloat16_rn(m2));
            mst_hi[cj * 32 + cb] = __float2bfloat16_rn(m2);
            mst_lo[cj * 32 + cb] = __float2bfloat16_rn(m2 - hif);
            m2f_s[cj * 32 + cb]  = m2;

            asm volatile("bar.sync 1, 128;" ::: "memory");
            // pack h-pairs -> global (tid<64): kp = 2*bid + hpair
            if (tid < 64) {
                const int hpair = tid >> 5, b = tid & 31;
                float h0 = __bfloat162float(mst_hi[(2 * hpair) * 32 + b]);
                float h1 = __bfloat162float(mst_hi[(2 * hpair + 1) * 32 + b]);
                float l0 = __bfloat162float(mst_lo[(2 * hpair) * 32 + b]);
                float l1 = __bfloat162float(mst_lo[(2 * hpair + 1) * 32 + b]);
                const int gi = nb * 256 * B_SZ + (2 * bid + hpair) * B_SZ + b;
                g_mP_hi[gi] = pack_bf2(h0, h1);
                g_mP_lo[gi] = pack_bf2(l0, l1);
            }
            // coalesced out: 32 threads write float4 (4 consecutive h per b)
            if (tid < 32) {
                float4 o4 = make_float4(m2f_s[tid], m2f_s[32 + tid],
                                        m2f_s[64 + tid], m2f_s[96 + tid]);
                *(float4*)&out[((size_t)s * B_SZ + tid) * H_SZ + h_base] = o4;
            }
            asm volatile("bar.sync 1, 128;" ::: "memory");
            if (tid == 0) { __threadfence(); atomicAdd(&g_bar, 1); }

            if (write_final && s == T_STEPS - 1) {
                size_t base = (size_t)T_STEPS * B_SZ * H_SZ;
                out[base + (size_t)cb * H_SZ + h_o] = m2;
                out[base + (size_t)B_SZ * H_SZ + (size_t)cb * H_SZ + h_o] = c2;
            }
        }

        // ---- grid barrier: R9 verbatim (all blocks spin) ----
        if (tid == 0) {
            const int target = NBLK * (s + 1);
            while (*(volatile int*)&g_bar < target) { }
            __threadfence();
        }
        __syncthreads();
    }
}

// ---------------- launch ----------------
extern "C" void kernel_launch(void* const* d_in, const int* in_sizes, int n_in,
                              void* d_out, int out_size)
{
    const float* input = (const float*)d_in[0];
    const float* padd  = (const float*)d_in[1];
    const float* W_x   = (const float*)d_in[2];
    const float* W_h   = (const float*)d_in[3];
    const float* bias  = (const float*)d_in[4];
    float* out = (float*)d_out;

    const size_t xp_smem = (size_t)XP_SMEM_FL * sizeof(float);
    cudaFuncSetAttribute(xproj_gemm, cudaFuncAttributeMaxDynamicSharedMemorySize, (int)xp_smem);
    cudaFuncSetAttribute(lstm_kernel, cudaFuncAttributeMaxDynamicSharedMemorySize, SMEM_BYTES_L);

    int write_final =
        ((size_t)out_size >= (size_t)T_STEPS * B_SZ * H_SZ + 2u * B_SZ * H_SZ) ? 1 : 0;

    xproj_gemm<<<dim3(G_SZ / 128, (T_STEPS * B_SZ) / 64), 256, xp_smem>>>(input, W_x, bias);
    lstm_kernel<<<NBLK, 512, SMEM_BYTES_L>>>(padd, W_h, out, write_final);
}

// round 14
// speedup vs baseline: 1.3999x; 1.1433x over previous
#include <cuda_runtime.h>
#include <cuda_bf16.h>
#include <cstdint>

#define T_STEPS 2048
#define B_SZ    32
#define D_SZ    512
#define H_SZ    512
#define G_SZ    2048
#define NBLK    128
#define GRP_B   16      // batch elements per group

// ---------------- device scratch ----------------
__device__ float g_xproj[(size_t)T_STEPS * G_SZ * B_SZ];     // [T][4H][B]
// m packed bf16 pairs per group: P[buf][grp][kp][b16], uint32 = (m[2kp],m[2kp+1])
__device__ uint32_t g_mP_hi[2 * 2 * 256 * GRP_B];
__device__ uint32_t g_mP_lo[2 * 2 * 256 * GRP_B];
__device__ int g_bars[64];    // counter per group at [grp*32] (separate lines)

// ---------------- helpers ----------------
#define CP_ASYNC16(dst_u32, src_ptr) \
    asm volatile("cp.async.cg.shared.global [%0], [%1], 16;\n" :: "r"(dst_u32), "l"(src_ptr))
#define CP_COMMIT() asm volatile("cp.async.commit_group;\n")
#define CP_WAIT(N)  asm volatile("cp.async.wait_group %0;\n" :: "n"(N))

__device__ __forceinline__ void mma_bf16(float& d0, float& d1, float& d2, float& d3,
                                         uint32_t a0, uint32_t a1, uint32_t a2, uint32_t a3,
                                         uint32_t b0, uint32_t b1) {
    asm volatile(
        "mma.sync.aligned.m16n8k16.row.col.f32.bf16.bf16.f32 "
        "{%0,%1,%2,%3},{%4,%5,%6,%7},{%8,%9},{%0,%1,%2,%3};"
        : "+f"(d0), "+f"(d1), "+f"(d2), "+f"(d3)
        : "r"(a0), "r"(a1), "r"(a2), "r"(a3), "r"(b0), "r"(b1));
}
__device__ __forceinline__ uint32_t pack_bf2(float a, float b) {
    __nv_bfloat162 t = __floats2bfloat162_rn(a, b);   // a -> low half
    return *(uint32_t*)&t;
}
__device__ __forceinline__ void split_pair(float f0, float f1, uint32_t& hi, uint32_t& lo) {
    float h0 = __bfloat162float(__float2bfloat16_rn(f0));
    float h1 = __bfloat162float(__float2bfloat16_rn(f1));
    hi = pack_bf2(h0, h1);
    lo = pack_bf2(f0 - h0, f1 - h1);
}

// ============ phase 1: x_proj GEMM (bf16-pair 3-mma k16, 3-stage) ============
#define XPA 2304
#define XPB 4352
#define XP_SMEM_FL (3 * (XPA + XPB))

__global__ __launch_bounds__(256, 2) void xproj_gemm(
    const float* __restrict__ A, const float* __restrict__ Bm,
    const float* __restrict__ bias)
{
    extern __shared__ float sm[];
    float* As = sm;
    float* Bs = sm + 3 * XPA;
    float* stage = Bs;

    const unsigned as_u32 = (unsigned)__cvta_generic_to_shared(As);
    const unsigned bs_u32 = (unsigned)__cvta_generic_to_shared(Bs);

    const int tid = threadIdx.x;

    if (blockIdx.x == 0 && blockIdx.y == 0) {   // fold reset
        for (int i = tid; i < 64; i += 256) g_bars[i] = 0;
        for (int i = tid; i < 2 * 2 * 256 * GRP_B; i += 256) { g_mP_hi[i] = 0u; g_mP_lo[i] = 0u; }
    }

    const int n0 = blockIdx.x * 128;
    const int m0 = blockIdx.y * 64;
    const int w   = tid >> 5;
    const int l   = tid & 31;
    const int gid = l >> 2;
    const int tig = l & 3;
    const int nw  = w * 16;

    auto issue = [&](int it, int buf) {
        const int kc = it * 32;
#pragma unroll
        for (int i = 0; i < 2; i++) {
            int idx = tid + i * 256;
            int m = idx >> 3, kq = (idx & 7) << 2;
            CP_ASYNC16(as_u32 + (unsigned)((buf * XPA + m * 36 + kq) * 4),
                       A + (size_t)(m0 + m) * D_SZ + kc + kq);
        }
#pragma unroll
        for (int i = 0; i < 4; i++) {
            int idx = tid + i * 256;
            int k = idx >> 5, nq = (idx & 31) << 2;
            CP_ASYNC16(bs_u32 + (unsigned)((buf * XPB + k * 136 + nq) * 4),
                       Bm + (size_t)(kc + k) * G_SZ + n0 + nq);
        }
        CP_COMMIT();
    };

    float acc[4][2][4];
#pragma unroll
    for (int mt = 0; mt < 4; mt++)
#pragma unroll
        for (int nt = 0; nt < 2; nt++)
#pragma unroll
            for (int r = 0; r < 4; r++) acc[mt][nt][r] = 0.0f;

    issue(0, 0);
    issue(1, 1);

#pragma unroll 1
    for (int it = 0; it < 16; it++) {
        if (it < 15) { CP_WAIT(1); } else { CP_WAIT(0); }
        __syncthreads();
        if (it + 2 < 16) issue(it + 2, (it + 2) % 3);

        const float* Ab = As + (it % 3) * XPA;
        const float* Bb = Bs + (it % 3) * XPB;

#pragma unroll
        for (int c = 0; c < 2; c++) {
            const int k0 = c * 16 + tig * 2;
            uint32_t bh[2][2], bl[2][2];
#pragma unroll
            for (int nt = 0; nt < 2; nt++) {
                const int n = nw + nt * 8 + gid;
                float b00 = Bb[k0 * 136 + n];
                float b01 = Bb[(k0 + 1) * 136 + n];
                float b10 = Bb[(k0 + 8) * 136 + n];
                float b11 = Bb[(k0 + 9) * 136 + n];
                split_pair(b00, b01, bh[nt][0], bl[nt][0]);
                split_pair(b10, b11, bh[nt][1], bl[nt][1]);
            }
#pragma unroll
            for (int mt = 0; mt < 4; mt++) {
                const int row0 = mt * 16 + gid;
                float2 f0 = *(const float2*)&Ab[row0 * 36 + k0];
                float2 f1 = *(const float2*)&Ab[(row0 + 8) * 36 + k0];
                float2 f2 = *(const float2*)&Ab[row0 * 36 + k0 + 8];
                float2 f3 = *(const float2*)&Ab[(row0 + 8) * 36 + k0 + 8];
                uint32_t ah0, al0, ah1, al1, ah2, al2, ah3, al3;
                split_pair(f0.x, f0.y, ah0, al0);
                split_pair(f1.x, f1.y, ah1, al1);
                split_pair(f2.x, f2.y, ah2, al2);
                split_pair(f3.x, f3.y, ah3, al3);
#pragma unroll
                for (int nt = 0; nt < 2; nt++) {
                    mma_bf16(acc[mt][nt][0], acc[mt][nt][1], acc[mt][nt][2], acc[mt][nt][3],
                             ah0, ah1, ah2, ah3, bh[nt][0], bh[nt][1]);
                    mma_bf16(acc[mt][nt][0], acc[mt][nt][1], acc[mt][nt][2], acc[mt][nt][3],
                             ah0, ah1, ah2, ah3, bl[nt][0], bl[nt][1]);
                    mma_bf16(acc[mt][nt][0], acc[mt][nt][1], acc[mt][nt][2], acc[mt][nt][3],
                             al0, al1, al2, al3, bh[nt][0], bh[nt][1]);
                }
            }
        }
    }
    __syncthreads();

#pragma unroll
    for (int mt = 0; mt < 4; mt++)
#pragma unroll
        for (int nt = 0; nt < 2; nt++) {
            int m = mt * 16 + gid;
            int n = nw + nt * 8 + tig * 2;
            stage[n * 68 + m]           = acc[mt][nt][0];
            stage[(n + 1) * 68 + m]     = acc[mt][nt][1];
            stage[n * 68 + m + 8]       = acc[mt][nt][2];
            stage[(n + 1) * 68 + m + 8] = acc[mt][nt][3];
        }
    __syncthreads();

#pragma unroll
    for (int i = 0; i < 8; i++) {
        int idx = tid + i * 256;
        int n = idx >> 4, mq = (idx & 15) << 2;
        float4 v = *(float4*)&stage[n * 68 + mq];
        float bb = bias[n0 + n];
        v.x += bb; v.y += bb; v.z += bb; v.w += bb;
        int mg = m0 + mq;
        int t = mg >> 5, b = mg & 31;
        *(float4*)&g_xproj[((size_t)t * G_SZ + n0 + n) * B_SZ + b] = v;
    }
}

// ============ phase 2: two independent 64-block group recurrences ===========
// group = bid>>6 owns b [grp*16, +16); block owns 8 h (32 gate cols). K-split 16.
#define MPS16 24                                   // u32 stride per kp row
#define MHI_OFF_B 0                                // 256*24*4 = 24576
#define MLO_OFF_B 24576
#define RED_OFF_B 49152                            // [16w][32cc][20] f32 = 40960
#define XP_OFF_B  90112                            // [2][32cc][16b] f32 = 4096
#define PAD_OFF_B 94208                            // [2][16] f32 = 128
#define M2F_OFF_B 94336                            // [8][16] f32 = 512
#define SMEM_BYTES_L 94848

__device__ __forceinline__ float fsig(float x)  { return 1.0f / (1.0f + __expf(-x)); }
__device__ __forceinline__ float ftanh(float x) { return 1.0f - 2.0f / (__expf(2.0f * x) + 1.0f); }

__global__ __launch_bounds__(512, 1) void lstm_kernel(
    const float* __restrict__ paddings,
    const float* __restrict__ W_h,
    float* __restrict__ out,
    int write_final)
{
    extern __shared__ char smc[];
    const uint32_t* mhi_s = (const uint32_t*)(smc + MHI_OFF_B);
    const uint32_t* mlo_s = (const uint32_t*)(smc + MLO_OFF_B);
    float* red   = (float*)(smc + RED_OFF_B);
    float* xp_s  = (float*)(smc + XP_OFF_B);
    float* pad_s = (float*)(smc + PAD_OFF_B);
    float* m2f_s = (float*)(smc + M2F_OFF_B);

    const unsigned smem_u32 = (unsigned)__cvta_generic_to_shared(smc);
    const unsigned mhi_u32  = smem_u32 + MHI_OFF_B;
    const unsigned mlo_u32  = smem_u32 + MLO_OFF_B;
    const unsigned xp_u32   = smem_u32 + XP_OFF_B;
    const unsigned pad_u32  = smem_u32 + PAD_OFF_B;

    const int tid  = threadIdx.x;
    const int bid  = blockIdx.x;
    const int grp  = bid >> 6;
    const int gbid = bid & 63;
    const int h_base = gbid * 8;

    const int l   = tid & 31;
    const int w   = tid >> 5;
    const int gid = l >> 2;
    const int tig = l & 3;

    // ---- W fragments (bf16 pairs): 32 cc = 4 n-tiles ----
    uint32_t Wh[2][4][2], Wl[2][4][2];
#pragma unroll
    for (int J = 0; J < 2; J++)
#pragma unroll
        for (int nt = 0; nt < 4; nt++)
#pragma unroll
            for (int r = 0; r < 2; r++) {
                int k  = w * 32 + J * 16 + tig * 2 + r * 8;
                int cc = nt * 8 + gid;
                int g  = cc & 3;
                int j8 = cc >> 2;              // 0..7
                const float* wp = W_h + (size_t)g * H_SZ + h_base + j8;
                float w0 = wp[(size_t)k * G_SZ];
                float w1 = wp[(size_t)(k + 1) * G_SZ];
                split_pair(w0, w1, Wh[J][nt][r], Wl[J][nt][r]);
            }

    // cell ownership (tid<128): cb = tid&15 (0..15), cj = tid>>4 (0..7)
    const int cb  = tid & 15;
    const int cj  = tid >> 4;
    const int h_o = h_base + cj;
    const int b_g = grp * GRP_B + cb;          // global batch index

    // xp loader coords (tid<128): 32cc x 16b, 16B granules
    const int xcc = tid >> 2;
    const int xq  = (tid & 3) << 2;
    const float* xp_src_base = g_xproj +
        ((size_t)((xcc & 3) * H_SZ + h_base + (xcc >> 2))) * B_SZ + grp * GRP_B + xq;

    // m loader coords: chunk row 64B; lane: row l>>2, 16B piece (l&3)
    const int mrow = l >> 2;
    const int mq16 = (l & 3) * 16;

    // prologue: xp(0) + pad(0)
    if (tid < 128)
        CP_ASYNC16(xp_u32 + (unsigned)((xcc * GRP_B + xq) * 4), xp_src_base);
    if (tid >= 128 && tid < 132)
        CP_ASYNC16(pad_u32 + (unsigned)((tid - 128) * 16),
                   paddings + grp * GRP_B + (tid - 128) * 4);
    CP_COMMIT();

    float c_reg = 0.0f, m_prev = 0.0f;
    int* my_bar = &g_bars[grp * 32];

#pragma unroll 1
    for (int s = 0; s < T_STEPS; s++) {
        const int pb = s & 1, nb = pb ^ 1;
        const char* srcP_hi = (const char*)(g_mP_hi + (pb * 2 + grp) * 256 * GRP_B);
        const char* srcP_lo = (const char*)(g_mP_lo + (pb * 2 + grp) * 256 * GRP_B);

        // ---- 2 warp-private m groups (coalesced: 512B per plane per chunk) ----
#pragma unroll
        for (int J = 0; J < 2; J++) {
            const int kp = w * 16 + J * 8 + mrow;
            const unsigned sb = (unsigned)(kp * 64 + mq16);
            const unsigned db = (unsigned)(kp * (MPS16 * 4) + mq16);
            CP_ASYNC16(mhi_u32 + db, srcP_hi + sb);
            CP_ASYNC16(mlo_u32 + db, srcP_lo + sb);
            CP_COMMIT();
        }
        // ---- xp(s+1)+pad(s+1) prefetch ----
        if (s + 1 < T_STEPS) {
            if (tid < 128)
                CP_ASYNC16(xp_u32 + (unsigned)(((nb * 512) + xcc * GRP_B + xq) * 4),
                           xp_src_base + (size_t)(s + 1) * G_SZ * B_SZ);
            if (tid >= 128 && tid < 132)
                CP_ASYNC16(pad_u32 + (unsigned)((nb * 16 + (tid - 128) * 4) * 4),
                           paddings + (size_t)(s + 1) * B_SZ + grp * GRP_B + (tid - 128) * 4);
        }
        CP_COMMIT();

        float acc1[4][4], acc2[4][4];
#pragma unroll
        for (int nt = 0; nt < 4; nt++)
#pragma unroll
            for (int r = 0; r < 4; r++) { acc1[nt][r] = 0.0f; acc2[nt][r] = 0.0f; }

        // ---- 2 mma chunks (M=16, N=32), warp-paced ----
#define MMA_CHUNK(J, WN)                                                           \
        {                                                                          \
            CP_WAIT(WN);                                                           \
            __syncwarp();                                                          \
            const int i0 = (w * 16 + (J) * 8 + tig) * MPS16 + gid;                 \
            const int i2 = i0 + 4 * MPS16;                                         \
            uint32_t ah0 = mhi_s[i0], ah1 = mhi_s[i0 + 8];                         \
            uint32_t ah2 = mhi_s[i2], ah3 = mhi_s[i2 + 8];                         \
            uint32_t al0 = mlo_s[i0], al1 = mlo_s[i0 + 8];                         \
            uint32_t al2 = mlo_s[i2], al3 = mlo_s[i2 + 8];                         \
            _Pragma("unroll")                                                      \
            for (int nt = 0; nt < 4; nt++) {                                       \
                mma_bf16(acc1[nt][0], acc1[nt][1], acc1[nt][2], acc1[nt][3],       \
                         ah0, ah1, ah2, ah3, Wh[J][nt][0], Wh[J][nt][1]);          \
                mma_bf16(acc2[nt][0], acc2[nt][1], acc2[nt][2], acc2[nt][3],       \
                         ah0, ah1, ah2, ah3, Wl[J][nt][0], Wl[J][nt][1]);          \
                mma_bf16(acc2[nt][0], acc2[nt][1], acc2[nt][2], acc2[nt][3],       \
                         al0, al1, al2, al3, Wh[J][nt][0], Wh[J][nt][1]);          \
            }                                                                      \
        }

        MMA_CHUNK(0, 2)
        MMA_CHUNK(1, 1)
#undef MMA_CHUNK

        // partials -> red[w][cc][20]
        {
            float* rp = red + w * 640;
#pragma unroll
            for (int nt = 0; nt < 4; nt++) {
                const int cc = nt * 8 + tig * 2;
                rp[cc * 20 + gid]           = acc1[nt][0] + acc2[nt][0];
                rp[(cc + 1) * 20 + gid]     = acc1[nt][1] + acc2[nt][1];
                rp[cc * 20 + gid + 8]       = acc1[nt][2] + acc2[nt][2];
                rp[(cc + 1) * 20 + gid + 8] = acc1[nt][3] + acc2[nt][3];
            }
        }
        __syncthreads();

        // ---- cell tail (tid<128: 8h x 16b) ----
        float m2 = 0.0f, c2 = 0.0f;
        if (tid < 128) {
            float gate[4];
#pragma unroll
            for (int g = 0; g < 4; g++) {
                const int cc = cj * 4 + g;
                const float* rb = red + cc * 20 + cb;
                float sum = xp_s[pb * 512 + cc * GRP_B + cb];
#pragma unroll
                for (int ww = 0; ww < 16; ww++) sum += rb[ww * 640];
                gate[g] = sum;
            }
            float p  = pad_s[pb * 16 + cb];
            float ii = fsig(gate[0]), ff = fsig(gate[1]);
            float gg = ftanh(gate[2]), oo = fsig(gate[3]);
            float cn = ff * c_reg + ii * gg;
            float mn = oo * ftanh(cn);
            m2 = mn + (m_prev - mn) * p;
            c2 = cn + (c_reg - cn) * p;
            c_reg = c2;
            m_prev = m2;

            m2f_s[cj * GRP_B + cb] = m2;

            // pack h-pair via shuffle: lanes l and l^16 hold (even cj, odd cj)
            float m2p = __shfl_xor_sync(0xffffffffu, m2, 16);
            if ((tid & 16) == 0) {     // even cj lane
                float he = __bfloat162float(__float2bfloat16_rn(m2));
                float ho = __bfloat162float(__float2bfloat16_rn(m2p));
                const int kp = gbid * 4 + w;       // (h_base + 2w)/2
                const int gi = ((nb * 2 + grp) * 256 + kp) * GRP_B + cb;
                g_mP_hi[gi] = pack_bf2(he, ho);
                g_mP_lo[gi] = pack_bf2(m2 - he, m2p - ho);
            }

            asm volatile("bar.sync 1, 128;" ::: "memory");
            // coalesced out: 32 threads, b = tid>>1, half = tid&1 -> float4
            if (tid < 32) {
                const int b = tid >> 1, half = tid & 1;
                float4 o4 = make_float4(m2f_s[(half * 4 + 0) * GRP_B + b],
                                        m2f_s[(half * 4 + 1) * GRP_B + b],
                                        m2f_s[(half * 4 + 2) * GRP_B + b],
                                        m2f_s[(half * 4 + 3) * GRP_B + b]);
                *(float4*)&out[((size_t)s * B_SZ + grp * GRP_B + b) * H_SZ
                               + h_base + half * 4] = o4;
            }
            if (tid == 0) { __threadfence(); atomicAdd(my_bar, 1); }

            if (write_final && s == T_STEPS - 1) {
                size_t base = (size_t)T_STEPS * B_SZ * H_SZ;
                out[base + (size_t)b_g * H_SZ + h_o] = m2;
                out[base + (size_t)B_SZ * H_SZ + (size_t)b_g * H_SZ + h_o] = c2;
            }
        }

        // ---- per-group grid barrier (all group blocks spin own counter) ----
        if (tid == 0) {
            const int target = 64 * (s + 1);
            while (*(volatile int*)my_bar < target) { }
            __threadfence();
        }
        __syncthreads();
    }
}

// ---------------- launch ----------------
extern "C" void kernel_launch(void* const* d_in, const int* in_sizes, int n_in,
                              void* d_out, int out_size)
{
    const float* input = (const float*)d_in[0];
    const float* padd  = (const float*)d_in[1];
    const float* W_x   = (const float*)d_in[2];
    const float* W_h   = (const float*)d_in[3];
    const float* bias  = (const float*)d_in[4];
    float* out = (float*)d_out;

    const size_t xp_smem = (size_t)XP_SMEM_FL * sizeof(float);
    cudaFuncSetAttribute(xproj_gemm, cudaFuncAttributeMaxDynamicSharedMemorySize, (int)xp_smem);
    cudaFuncSetAttribute(lstm_kernel, cudaFuncAttributeMaxDynamicSharedMemorySize, SMEM_BYTES_L);

    int write_final =
        ((size_t)out_size >= (size_t)T_STEPS * B_SZ * H_SZ + 2u * B_SZ * H_SZ) ? 1 : 0;

    xproj_gemm<<<dim3(G_SZ / 128, (T_STEPS * B_SZ) / 64), 256, xp_smem>>>(input, W_x, bias);
    lstm_kernel<<<NBLK, 512, SMEM_BYTES_L>>>(padd, W_h, out, write_final);
}